// round 3
// baseline (speedup 1.0000x reference)
#include <cuda_runtime.h>

#define Bz 64
#define Tz 512
#define Iz 128
#define Hz 512
#define Gz 2048          // 4*H
#define BTz (Bz*Tz)      // 32768
#define BHs (Bz*Hz)      // 32768

#define NBLK 128
#define NTHR 256

// Scratch (static device globals)
__device__ float g_XG[(size_t)BTz * Gz];     // 256 MiB: input-gate projections
__device__ float g_HSEQ[(size_t)BTz * Hz];   // 64 MiB: layer-0 hidden sequence
__device__ float g_PART[4 * Gz * Bz];        // [ks][gc][b] split-K partials
__device__ float g_HT[Hz * Bz];              // transposed hidden state hT[k][b]
__device__ unsigned g_count;                  // grid barrier state (zero-init)
__device__ unsigned g_sense;

// ---------------- grid barrier (sense reversal) ----------------
__device__ __forceinline__ void grid_barrier(unsigned sense_val) {
    __syncthreads();
    if (threadIdx.x == 0) {
        __threadfence();
        unsigned arr = atomicAdd(&g_count, 1u);
        if (arr == NBLK - 1) {
            g_count = 0;
            __threadfence();
            asm volatile("st.release.gpu.u32 [%0], %1;" ::
                         "l"(&g_sense), "r"(sense_val) : "memory");
        } else {
            unsigned v;
            do {
                asm volatile("ld.acquire.gpu.u32 %0, [%1];"
                             : "=r"(v) : "l"(&g_sense) : "memory");
            } while (v != sense_val);
        }
    }
    __syncthreads();
}

// ---------------- big input-projection GEMM ----------------
// C[M,N] = A[M,K] @ W[N,K]^T + bias0[n] + bias1[n]; tile 64x64, BK=16.
__global__ __launch_bounds__(256) void gemm_nt(
    float* __restrict__ C, const float* __restrict__ A, const float* __restrict__ W,
    int lda, int ldw, int ldc, int K,
    const float* __restrict__ bias0, const float* __restrict__ bias1)
{
    __shared__ float As[16][68];
    __shared__ float Ws[16][68];
    const int tid = threadIdx.x;
    const int tx = tid & 15, ty = tid >> 4;
    const int bn = blockIdx.x, bm = blockIdx.y;
    const float* Ab = A + (size_t)(bm * 64) * lda;
    const float* Wb = W + (size_t)(bn * 64) * ldw;
    const int lr = tid >> 2;
    const int lc = (tid & 3) << 2;

    float acc[4][4] = {};

    for (int kt = 0; kt < K; kt += 16) {
        float4 av = *(const float4*)(Ab + (size_t)lr * lda + kt + lc);
        float4 wv = *(const float4*)(Wb + (size_t)lr * ldw + kt + lc);
        As[lc + 0][lr] = av.x; As[lc + 1][lr] = av.y;
        As[lc + 2][lr] = av.z; As[lc + 3][lr] = av.w;
        Ws[lc + 0][lr] = wv.x; Ws[lc + 1][lr] = wv.y;
        Ws[lc + 2][lr] = wv.z; Ws[lc + 3][lr] = wv.w;
        __syncthreads();
#pragma unroll
        for (int kk = 0; kk < 16; kk++) {
            float4 a4 = *(const float4*)&As[kk][ty * 4];
            float4 w4 = *(const float4*)&Ws[kk][tx * 4];
            float ar[4] = {a4.x, a4.y, a4.z, a4.w};
            float wr[4] = {w4.x, w4.y, w4.z, w4.w};
#pragma unroll
            for (int i = 0; i < 4; i++)
#pragma unroll
                for (int j = 0; j < 4; j++)
                    acc[i][j] += ar[i] * wr[j];
        }
        __syncthreads();
    }

    float* Cb = C + (size_t)(bm * 64) * ldc + bn * 64;
#pragma unroll
    for (int i = 0; i < 4; i++)
#pragma unroll
        for (int j = 0; j < 4; j++) {
            int m = ty * 4 + i, n = tx * 4 + j;
            Cb[(size_t)m * ldc + n] = acc[i][j] + bias0[bn * 64 + n] + bias1[bn * 64 + n];
        }
}

// ---------------- persistent LSTM layer (all 512 timesteps) ----------------
// Grid: 128 blocks x 256 threads. Block (jg, ks): jg = bid>>2 owns 16 j-cols
// (64 gate-cols), ks = bid&3 owns K-slice [ks*128, ks*128+128).
// Phase A: partial gates -> g_PART.  Phase B: block bid owns j in
// [bid*4, bid*4+4), all 64 batches; c-state in registers across steps.
__global__ void __launch_bounds__(NTHR, 1) lstm_layer_persist(
    const float* __restrict__ whh,    // [2048][512]
    const float* __restrict__ xg,     // [B*T][2048] (+biases already)
    const float* __restrict__ hxl,    // [64][512] initial h
    const float* __restrict__ cxl,    // [64][512] initial c
    float* __restrict__ hseq,         // [B*T][512] or nullptr
    float* __restrict__ hn_out,       // [64][512]
    float* __restrict__ cn_out)       // [64][512]
{
    extern __shared__ float smem[];
    float* w_sT = smem;               // [128 k][64 gcl]
    float* h_s  = smem + 128 * 64;    // [128 k][64 b]

    const int tid = threadIdx.x;
    const int bid = blockIdx.x;
    const int jg = bid >> 2;
    const int ks = bid & 3;
    const int k0 = ks * 128;
    const int jgbase = jg * 16;

    // Cache this block's w_hh slice in SMEM (transposed): w_sT[k][gcl],
    // gcl = g*16 + jj  ->  w_hh row g*512 + jgbase + jj, col k0+k.
    for (int i = tid; i < 64 * 128; i += NTHR) {
        int gcl = i >> 7;
        int k = i & 127;
        int g = gcl >> 4, jj = gcl & 15;
        w_sT[k * 64 + gcl] = whh[(size_t)(g * 512 + jgbase + jj) * Hz + k0 + k];
    }

    // Phase-B identity & persistent cell state
    const int pb_b = tid >> 2;          // 0..63
    const int pb_j = bid * 4 + (tid & 3);
    float c_reg = cxl[pb_b * Hz + pb_j];
    g_HT[pb_j * Bz + pb_b] = hxl[pb_b * Hz + pb_j];

    unsigned sense = 0;
    sense ^= 1; grid_barrier(sense);     // h init visible everywhere

    const int b0 = (tid & 15) * 4;
    const int gcl0 = (tid >> 4) * 4;     // 4 consecutive gate-cols, same gate
    const int gc_glob0 = (gcl0 >> 4) * 512 + jgbase + (gcl0 & 15);

    float hlast = 0.0f;

    for (int t = 0; t < Tz; t++) {
        // ---- stage h slice: h_s[k][b] = hT[k0+k][b] (contiguous copy) ----
        {
            const float4* src = (const float4*)(g_HT + (size_t)k0 * Bz);
            float4* dst = (float4*)h_s;
#pragma unroll
            for (int i = 0; i < (128 * 64 / 4) / NTHR; i++)
                dst[tid + i * NTHR] = src[tid + i * NTHR];
        }
        __syncthreads();

        // ---- Phase A: acc[i][j] = sum_k w[gcl0+i][k] * h[b0+j][k] ----
        float acc[4][4] = {};
#pragma unroll 4
        for (int k = 0; k < 128; k++) {
            float4 hv = *(const float4*)(h_s + k * 64 + b0);
            float4 wv = *(const float4*)(w_sT + k * 64 + gcl0);
            float hr[4] = {hv.x, hv.y, hv.z, hv.w};
            float wr[4] = {wv.x, wv.y, wv.z, wv.w};
#pragma unroll
            for (int i = 0; i < 4; i++)
#pragma unroll
                for (int j = 0; j < 4; j++)
                    acc[i][j] += wr[i] * hr[j];
        }
#pragma unroll
        for (int i = 0; i < 4; i++) {
            int gc = gc_glob0 + i;   // same gate group; jj advances by 1
            float4 v = make_float4(acc[i][0], acc[i][1], acc[i][2], acc[i][3]);
            *(float4*)(g_PART + ((size_t)ks * Gz + gc) * Bz + b0) = v;
        }
        __syncthreads();
        sense ^= 1; grid_barrier(sense);

        // ---- Phase B: gate sums + cell update for (pb_b, pb_j) ----
        {
            const float* xr = xg + ((size_t)pb_b * Tz + t) * Gz;
            float gsum[4];
#pragma unroll
            for (int g = 0; g < 4; g++) {
                int gc = g * 512 + pb_j;
                float s = xr[gc];
#pragma unroll
                for (int z = 0; z < 4; z++)
                    s += g_PART[((size_t)z * Gz + gc) * Bz + pb_b];
                gsum[g] = s;
            }
            float ig = 1.0f / (1.0f + expf(-gsum[0]));
            float fg = 1.0f / (1.0f + expf(-gsum[1]));
            float gg = tanhf(gsum[2]);
            float og = 1.0f / (1.0f + expf(-gsum[3]));
            c_reg = fg * c_reg + ig * gg;
            float hnew = og * tanhf(c_reg);
            hlast = hnew;
            g_HT[pb_j * Bz + pb_b] = hnew;
            if (hseq) hseq[((size_t)pb_b * Tz + t) * Hz + pb_j] = hnew;
        }
        sense ^= 1; grid_barrier(sense);
    }

    hn_out[pb_b * Hz + pb_j] = hlast;
    cn_out[pb_b * Hz + pb_j] = c_reg;

    sense ^= 1; grid_barrier(sense);   // closing barrier: even total (1026)
}

// ---------------- FC head: out[b] = dot(h1[b,:], fc_w) + fc_b ----------------
__global__ __launch_bounds__(256) void fc_kernel(
    float* __restrict__ out, const float* __restrict__ h,
    const float* __restrict__ w, const float* __restrict__ bb)
{
    int b = blockIdx.x;
    float s = 0.0f;
    for (int k = threadIdx.x; k < Hz; k += blockDim.x)
        s += h[(size_t)b * Hz + k] * w[k];
#pragma unroll
    for (int o = 16; o > 0; o >>= 1)
        s += __shfl_xor_sync(0xFFFFFFFFu, s, o);
    __shared__ float red[8];
    int wid = threadIdx.x >> 5, lane = threadIdx.x & 31;
    if (lane == 0) red[wid] = s;
    __syncthreads();
    if (threadIdx.x == 0) {
        float t = 0.0f;
#pragma unroll
        for (int i = 0; i < 8; i++) t += red[i];
        out[b] = t + bb[0];
    }
}

extern "C" void kernel_launch(void* const* d_in, const int* in_sizes, int n_in,
                              void* d_out, int out_size) {
    (void)in_sizes; (void)n_in; (void)out_size;
    const float* x    = (const float*)d_in[0];
    const float* hx   = (const float*)d_in[1];
    const float* cx   = (const float*)d_in[2];
    const float* wih0 = (const float*)d_in[3];
    const float* whh0 = (const float*)d_in[4];
    const float* bih0 = (const float*)d_in[5];
    const float* bhh0 = (const float*)d_in[6];
    const float* wih1 = (const float*)d_in[7];
    const float* whh1 = (const float*)d_in[8];
    const float* bih1 = (const float*)d_in[9];
    const float* bhh1 = (const float*)d_in[10];
    const float* fcw  = (const float*)d_in[11];
    const float* fcb  = (const float*)d_in[12];
    float* out = (float*)d_out;

    void *vXG, *vHS;
    cudaGetSymbolAddress(&vXG, g_XG);
    cudaGetSymbolAddress(&vHS, g_HSEQ);
    float* XG = (float*)vXG;
    float* HS = (float*)vHS;

    static bool attr_set = false;
    if (!attr_set) {
        cudaFuncSetAttribute(lstm_layer_persist,
                             cudaFuncAttributeMaxDynamicSharedMemorySize,
                             2 * 128 * 64 * (int)sizeof(float));
        attr_set = true;
    }
    const int smem_bytes = 2 * 128 * 64 * (int)sizeof(float);  // 64 KiB

    // Output packing: [out(64) | hn(2*B*H) | cn(2*B*H)]
    float* hn = out + Bz;
    float* cn = out + Bz + 2 * BHs;

    // ---- Layer 0 ----
    gemm_nt<<<dim3(Gz / 64, BTz / 64), 256>>>(
        XG, x, wih0, Iz, Iz, Gz, Iz, bih0, bhh0);
    lstm_layer_persist<<<NBLK, NTHR, smem_bytes>>>(
        whh0, XG, hx, cx, HS, hn, cn);

    // ---- Layer 1 ----
    gemm_nt<<<dim3(Gz / 64, BTz / 64), 256>>>(
        XG, HS, wih1, Hz, Hz, Gz, Hz, bih1, bhh1);
    lstm_layer_persist<<<NBLK, NTHR, smem_bytes>>>(
        whh1, XG, hx + BHs, cx + BHs, nullptr, hn + BHs, cn + BHs);

    // ---- FC head (reads layer-1 hn already in out buffer) ----
    fc_kernel<<<Bz, 256>>>(out, hn + BHs, fcw, fcb);
}

// round 4
// speedup vs baseline: 1.1125x; 1.1125x over previous
#include <cuda_runtime.h>

#define Bz 64
#define Tz 512
#define Iz 128
#define Hz 512
#define Gz 2048          // 4*H
#define BTz (Bz*Tz)      // 32768
#define BHs (Bz*Hz)      // 32768

#define NBLK 128
#define NTHR 512

// Scratch (static device globals)
__device__ float g_XG[(size_t)BTz * Gz];     // 256 MiB: input-gate projections
__device__ float g_HSEQ[(size_t)BTz * Hz];   // 64 MiB: layer-0 hidden sequence
__device__ float g_PART[8 * Gz * Bz];        // [z][gc][b] split-K partials (8 slots)
__device__ float g_HT[Hz * Bz];              // transposed hidden state hT[k][b]
__device__ unsigned g_count;                 // grid barrier state (zero-init)
__device__ unsigned g_sense;

// ---------------- grid barrier (sense reversal) ----------------
__device__ __forceinline__ void grid_barrier(unsigned sense_val) {
    __syncthreads();
    if (threadIdx.x == 0) {
        __threadfence();
        unsigned arr = atomicAdd(&g_count, 1u);
        if (arr == NBLK - 1) {
            g_count = 0;
            __threadfence();
            asm volatile("st.release.gpu.u32 [%0], %1;" ::
                         "l"(&g_sense), "r"(sense_val) : "memory");
        } else {
            unsigned v;
            do {
                asm volatile("ld.acquire.gpu.u32 %0, [%1];"
                             : "=r"(v) : "l"(&g_sense) : "memory");
            } while (v != sense_val);
        }
    }
    __syncthreads();
}

// ---------------- big input-projection GEMM ----------------
// C[M,N] = A[M,K] @ W[N,K]^T + bias0[n] + bias1[n]
// Tile 128x64, BK=16, 256 threads, 8x4 register micro-tile.
__global__ __launch_bounds__(256) void gemm_nt(
    float* __restrict__ C, const float* __restrict__ A, const float* __restrict__ W,
    int lda, int ldw, int ldc, int K,
    const float* __restrict__ bias0, const float* __restrict__ bias1)
{
    __shared__ float As[16][136];   // [k][m], padded
    __shared__ float Ws[16][68];    // [k][n], padded
    const int tid = threadIdx.x;
    const int tx = tid & 15;        // n-group (4 cols)
    const int ty = tid >> 4;        // m-group (8 rows)
    const int bn = blockIdx.x, bm = blockIdx.y;
    const float* Ab = A + (size_t)(bm * 128) * lda;
    const float* Wb = W + (size_t)(bn * 64) * ldw;
    const int lr = tid >> 2;        // 0..63
    const int lc = (tid & 3) << 2;  // 0,4,8,12

    float acc[8][4] = {};

    for (int kt = 0; kt < K; kt += 16) {
        // load A tile 128x16 (2 float4/thread) and W tile 64x16 (1 float4/thread)
#pragma unroll
        for (int half = 0; half < 2; half++) {
            int row = lr + half * 64;
            float4 av = *(const float4*)(Ab + (size_t)row * lda + kt + lc);
            As[lc + 0][row] = av.x; As[lc + 1][row] = av.y;
            As[lc + 2][row] = av.z; As[lc + 3][row] = av.w;
        }
        {
            float4 wv = *(const float4*)(Wb + (size_t)lr * ldw + kt + lc);
            Ws[lc + 0][lr] = wv.x; Ws[lc + 1][lr] = wv.y;
            Ws[lc + 2][lr] = wv.z; Ws[lc + 3][lr] = wv.w;
        }
        __syncthreads();
#pragma unroll
        for (int kk = 0; kk < 16; kk++) {
            float4 a0 = *(const float4*)&As[kk][ty * 8];
            float4 a1 = *(const float4*)&As[kk][ty * 8 + 4];
            float4 w4 = *(const float4*)&Ws[kk][tx * 4];
            float ar[8] = {a0.x, a0.y, a0.z, a0.w, a1.x, a1.y, a1.z, a1.w};
            float wr[4] = {w4.x, w4.y, w4.z, w4.w};
#pragma unroll
            for (int i = 0; i < 8; i++)
#pragma unroll
                for (int j = 0; j < 4; j++)
                    acc[i][j] += ar[i] * wr[j];
        }
        __syncthreads();
    }

    float* Cb = C + (size_t)(bm * 128) * ldc + bn * 64;
    float4 bv;
    {
        float4 b0v = *(const float4*)(bias0 + bn * 64 + tx * 4);
        float4 b1v = *(const float4*)(bias1 + bn * 64 + tx * 4);
        bv = make_float4(b0v.x + b1v.x, b0v.y + b1v.y, b0v.z + b1v.z, b0v.w + b1v.w);
    }
#pragma unroll
    for (int i = 0; i < 8; i++) {
        int m = ty * 8 + i;
        float4 v = make_float4(acc[i][0] + bv.x, acc[i][1] + bv.y,
                               acc[i][2] + bv.z, acc[i][3] + bv.w);
        *(float4*)(Cb + (size_t)m * ldc + tx * 4) = v;
    }
}

// ---------------- persistent LSTM layer (all 512 timesteps) ----------------
// Grid: 128 blocks x 512 threads. Block (jg, ks): jg = bid>>2 owns 16 j-cols
// (64 gate-cols), ks = bid&3 owns K-slice [ks*128, ks*128+128).
// Phase A: 512 threads split the K-slice in two halves (kh = tid>>8, 64 k each);
// each half writes its own partial slot z = ks*2+kh (8 slots total).
// Phase B: threads 0..255 own cell (b, j) with j in [bid*4, bid*4+4);
// c-state lives in registers across all steps.
__global__ void __launch_bounds__(NTHR, 1) lstm_layer_persist(
    const float* __restrict__ whh,    // [2048][512]
    const float* __restrict__ xg,     // [B*T][2048] (+biases already)
    const float* __restrict__ hxl,    // [64][512] initial h
    const float* __restrict__ cxl,    // [64][512] initial c
    float* __restrict__ hseq,         // [B*T][512] or nullptr
    float* __restrict__ hn_out,       // [64][512]
    float* __restrict__ cn_out)       // [64][512]
{
    extern __shared__ float smem[];
    float* w_sT = smem;               // [128 k][64 gcl]
    float* h_s  = smem + 128 * 64;    // [128 k][64 b]

    const int tid = threadIdx.x;
    const int bid = blockIdx.x;
    const int jg = bid >> 2;
    const int ks = bid & 3;
    const int k0 = ks * 128;
    const int jgbase = jg * 16;

    // Cache this block's w_hh slice in SMEM (transposed): w_sT[k][gcl],
    // gcl = g*16 + jj  ->  w_hh row g*512 + jgbase + jj, col k0+k.
    for (int i = tid; i < 64 * 128; i += NTHR) {
        int gcl = i >> 7;
        int k = i & 127;
        int g = gcl >> 4, jj = gcl & 15;
        w_sT[k * 64 + gcl] = whh[(size_t)(g * 512 + jgbase + jj) * Hz + k0 + k];
    }

    // Phase-B identity & persistent cell state (threads 0..255)
    const int pb_b = (tid & 255) >> 2;
    const int pb_j = bid * 4 + (tid & 3);
    float c_reg = 0.0f;
    if (tid < 256) {
        c_reg = cxl[pb_b * Hz + pb_j];
        g_HT[pb_j * Bz + pb_b] = hxl[pb_b * Hz + pb_j];
    }

    unsigned sense = 0;
    sense ^= 1; grid_barrier(sense);     // h init visible everywhere

    // Phase-A identity: kh = K-half, t8 picks (gcl0, b0) micro-tile
    const int kh = tid >> 8;             // 0 or 1
    const int t8 = tid & 255;
    const int b0 = (t8 & 15) * 4;
    const int gcl0 = (t8 >> 4) * 4;      // 4 consecutive gate-cols, same gate
    const int gc_glob0 = (gcl0 >> 4) * 512 + jgbase + (gcl0 & 15);
    const int zslot = ks * 2 + kh;
    const float* wbase = w_sT + (size_t)kh * 64 * 64;  // k-half offset
    const float* hbase = h_s  + (size_t)kh * 64 * 64;

    float hlast = 0.0f;

    for (int t = 0; t < Tz; t++) {
        // ---- stage h slice: h_s[k][b] = hT[k0+k][b] (contiguous copy) ----
        {
            const float4* src = (const float4*)(g_HT + (size_t)k0 * Bz);
            float4* dst = (float4*)h_s;
#pragma unroll
            for (int i = 0; i < (128 * 64 / 4) / NTHR; i++)
                dst[tid + i * NTHR] = src[tid + i * NTHR];
        }
        __syncthreads();

        // ---- Phase A: acc[i][j] = sum over this thread's 64 k ----
        float acc[4][4] = {};
#pragma unroll 4
        for (int k = 0; k < 64; k++) {
            float4 hv = *(const float4*)(hbase + k * 64 + b0);
            float4 wv = *(const float4*)(wbase + k * 64 + gcl0);
            float hr[4] = {hv.x, hv.y, hv.z, hv.w};
            float wr[4] = {wv.x, wv.y, wv.z, wv.w};
#pragma unroll
            for (int i = 0; i < 4; i++)
#pragma unroll
                for (int j = 0; j < 4; j++)
                    acc[i][j] += wr[i] * hr[j];
        }
#pragma unroll
        for (int i = 0; i < 4; i++) {
            int gc = gc_glob0 + i;   // same gate group; jj advances by 1
            float4 v = make_float4(acc[i][0], acc[i][1], acc[i][2], acc[i][3]);
            *(float4*)(g_PART + ((size_t)zslot * Gz + gc) * Bz + b0) = v;
        }
        sense ^= 1; grid_barrier(sense);

        // ---- Phase B: gate sums + cell update for (pb_b, pb_j) ----
        if (tid < 256) {
            const float* xr = xg + ((size_t)pb_b * Tz + t) * Gz;
            float gsum[4];
#pragma unroll
            for (int g = 0; g < 4; g++) {
                int gc = g * 512 + pb_j;
                float s = xr[gc];
#pragma unroll
                for (int z = 0; z < 8; z++)
                    s += g_PART[((size_t)z * Gz + gc) * Bz + pb_b];
                gsum[g] = s;
            }
            float ig = 1.0f / (1.0f + expf(-gsum[0]));
            float fg = 1.0f / (1.0f + expf(-gsum[1]));
            float gg = tanhf(gsum[2]);
            float og = 1.0f / (1.0f + expf(-gsum[3]));
            c_reg = fg * c_reg + ig * gg;
            float hnew = og * tanhf(c_reg);
            hlast = hnew;
            g_HT[pb_j * Bz + pb_b] = hnew;
            if (hseq) hseq[((size_t)pb_b * Tz + t) * Hz + pb_j] = hnew;
        }
        sense ^= 1; grid_barrier(sense);
    }

    if (tid < 256) {
        hn_out[pb_b * Hz + pb_j] = hlast;
        cn_out[pb_b * Hz + pb_j] = c_reg;
    }

    sense ^= 1; grid_barrier(sense);   // closing barrier: total 1026 (even)
}

// ---------------- FC head: out[b] = dot(h1[b,:], fc_w) + fc_b ----------------
__global__ __launch_bounds__(256) void fc_kernel(
    float* __restrict__ out, const float* __restrict__ h,
    const float* __restrict__ w, const float* __restrict__ bb)
{
    int b = blockIdx.x;
    float s = 0.0f;
    for (int k = threadIdx.x; k < Hz; k += blockDim.x)
        s += h[(size_t)b * Hz + k] * w[k];
#pragma unroll
    for (int o = 16; o > 0; o >>= 1)
        s += __shfl_xor_sync(0xFFFFFFFFu, s, o);
    __shared__ float red[8];
    int wid = threadIdx.x >> 5, lane = threadIdx.x & 31;
    if (lane == 0) red[wid] = s;
    __syncthreads();
    if (threadIdx.x == 0) {
        float t = 0.0f;
#pragma unroll
        for (int i = 0; i < 8; i++) t += red[i];
        out[b] = t + bb[0];
    }
}

extern "C" void kernel_launch(void* const* d_in, const int* in_sizes, int n_in,
                              void* d_out, int out_size) {
    (void)in_sizes; (void)n_in; (void)out_size;
    const float* x    = (const float*)d_in[0];
    const float* hx   = (const float*)d_in[1];
    const float* cx   = (const float*)d_in[2];
    const float* wih0 = (const float*)d_in[3];
    const float* whh0 = (const float*)d_in[4];
    const float* bih0 = (const float*)d_in[5];
    const float* bhh0 = (const float*)d_in[6];
    const float* wih1 = (const float*)d_in[7];
    const float* whh1 = (const float*)d_in[8];
    const float* bih1 = (const float*)d_in[9];
    const float* bhh1 = (const float*)d_in[10];
    const float* fcw  = (const float*)d_in[11];
    const float* fcb  = (const float*)d_in[12];
    float* out = (float*)d_out;

    void *vXG, *vHS;
    cudaGetSymbolAddress(&vXG, g_XG);
    cudaGetSymbolAddress(&vHS, g_HSEQ);
    float* XG = (float*)vXG;
    float* HS = (float*)vHS;

    static bool attr_set = false;
    if (!attr_set) {
        cudaFuncSetAttribute(lstm_layer_persist,
                             cudaFuncAttributeMaxDynamicSharedMemorySize,
                             2 * 128 * 64 * (int)sizeof(float));
        attr_set = true;
    }
    const int smem_bytes = 2 * 128 * 64 * (int)sizeof(float);  // 64 KiB

    // Output packing: [out(64) | hn(2*B*H) | cn(2*B*H)]
    float* hn = out + Bz;
    float* cn = out + Bz + 2 * BHs;

    // ---- Layer 0 ----
    gemm_nt<<<dim3(Gz / 64, BTz / 128), 256>>>(
        XG, x, wih0, Iz, Iz, Gz, Iz, bih0, bhh0);
    lstm_layer_persist<<<NBLK, NTHR, smem_bytes>>>(
        whh0, XG, hx, cx, HS, hn, cn);

    // ---- Layer 1 ----
    gemm_nt<<<dim3(Gz / 64, BTz / 128), 256>>>(
        XG, HS, wih1, Hz, Hz, Gz, Hz, bih1, bhh1);
    lstm_layer_persist<<<NBLK, NTHR, smem_bytes>>>(
        whh1, XG, hx + BHs, cx + BHs, nullptr, hn + BHs, cn + BHs);

    // ---- FC head (reads layer-1 hn already in out buffer) ----
    fc_kernel<<<Bz, 256>>>(out, hn + BHs, fcw, fcb);
}